// round 12
// baseline (speedup 1.0000x reference)
#include <cuda_runtime.h>
#include <cuda_bf16.h>
#include <cstdint>
#include <math.h>

typedef unsigned int u32;

// ---------------- problem constants ----------------
#define T_TOK   2048
#define HID     4096
#define NH      32
#define NKH     8
#define HD      128
#define VDIM    64
#define QKV_N   (NH*HD + NKH*HD + NKH*VDIM)   // 5632
#define K_OFF   (NH*HD)                        // 4096
#define V_OFF   (NH*HD + NKH*HD)               // 5120
#define WINDOW_SZ 1024
#define SCALE_ATTN 0.08838834764831845f        // 128^-0.5
#define V_SCALE_C  1.25f

// ---------------- scratch (no allocs allowed) ----------------
__device__ float g_qkv [T_TOK * QKV_N];
__device__ float g_attn[T_TOK * NH * VDIM];
__device__ uint4 g_kp[NKH * T_TOK * 32];            // prepacked K (8 MB)
__device__ uint4 g_vt[NKH * (T_TOK/2) * 2 * 16];    // prepacked V (4 MB)
__device__ float g_hid_t [T_TOK * HID];             // tf32-rounded hidden
__device__ float g_wqkv_t[HID * QKV_N];             // tf32-rounded Wqkv
__device__ float g_wo_t  [NH*VDIM * HID];           // tf32-rounded Wo

// =====================================================================
// helpers
// =====================================================================
__device__ __forceinline__ u32 f2tf32(float f) {
    u32 r;
    asm("cvt.rna.tf32.f32 %0, %1;" : "=r"(r) : "f"(f));
    return r;
}

__device__ __forceinline__ void mma_tf32(float c[4], const u32 a[4],
                                         const u32 b[2]) {
    asm volatile(
        "mma.sync.aligned.m16n8k8.row.col.f32.tf32.tf32.f32 "
        "{%0,%1,%2,%3}, {%4,%5,%6,%7}, {%8,%9}, {%0,%1,%2,%3};\n"
        : "+f"(c[0]), "+f"(c[1]), "+f"(c[2]), "+f"(c[3])
        : "r"(a[0]), "r"(a[1]), "r"(a[2]), "r"(a[3]), "r"(b[0]), "r"(b[1]));
}

__device__ __forceinline__ void mma_bf16(float c[4], const u32 a[4],
                                         const u32 b[2]) {
    asm volatile(
        "mma.sync.aligned.m16n8k16.row.col.f32.bf16.bf16.f32 "
        "{%0,%1,%2,%3}, {%4,%5,%6,%7}, {%8,%9}, {%0,%1,%2,%3};\n"
        : "+f"(c[0]), "+f"(c[1]), "+f"(c[2]), "+f"(c[3])
        : "r"(a[0]), "r"(a[1]), "r"(a[2]), "r"(a[3]), "r"(b[0]), "r"(b[1]));
}

__device__ __forceinline__ void split2(float x, float y, u32& hi, u32& lo) {
    u32 bx = __float_as_uint(x), by = __float_as_uint(y);
    hi = __byte_perm(bx, by, 0x7632);
    float lx = x - __uint_as_float(bx & 0xffff0000u);
    float ly = y - __uint_as_float(by & 0xffff0000u);
    lo = __byte_perm(__float_as_uint(lx), __float_as_uint(ly), 0x7632);
}

__device__ __forceinline__ void cp16(void* smem_dst, const void* gmem_src) {
    u32 s = (u32)__cvta_generic_to_shared(smem_dst);
    asm volatile("cp.async.ca.shared.global [%0], [%1], 16;\n"
                 :: "r"(s), "l"(gmem_src));
}
#define CP_COMMIT() asm volatile("cp.async.commit_group;\n" ::: "memory")
#define CP_WAIT(N)  asm volatile("cp.async.wait_group %0;\n" :: "n"(N) : "memory")

// =====================================================================
// Round fp32 -> tf32 (stored as fp32 bits), elementwise. n4 = elems/4.
// =====================================================================
__global__ __launch_bounds__(256) void tf32_round_kernel(
    const float* __restrict__ in, float* __restrict__ out, int n4)
{
    int i = blockIdx.x * 256 + threadIdx.x;
    if (i < n4) {
        float4 v = ((const float4*)in)[i];
        v.x = __uint_as_float(f2tf32(v.x));
        v.y = __uint_as_float(f2tf32(v.y));
        v.z = __uint_as_float(f2tf32(v.z));
        v.w = __uint_as_float(f2tf32(v.w));
        ((float4*)out)[i] = v;
    }
}

// =====================================================================
// TF32 GEMM, pre-rounded inputs, cp.async 3-stage pipeline.
// C[M,N] = A[M,K] @ B[K,N]; 128x128 block tile, BK=32,
// 4 warps in 2x2, warp tile 64x64 (32 HMMA per k8-step per warp).
// =====================================================================
#define GBM 128
#define GBN 128
#define GBK 32
#define AS_STRIDE 36
#define BS_STRIDE 132
#define A_STG (GBM*AS_STRIDE)          // 4608 u32
#define B_STG (GBK*BS_STRIDE)          // 4224 u32
#define STG_ELEMS (A_STG + B_STG)      // 8832 u32
#define GEMM_SMEM (3 * STG_ELEMS * 4)  // 105984 B

__global__ __launch_bounds__(128) void gemm_tf32_kernel(
    const float* __restrict__ A, const float* __restrict__ B,
    float* __restrict__ C, int M, int N, int K)
{
    extern __shared__ u32 smem_u[];

    const int tid  = threadIdx.x;
    const int warp = tid >> 5;
    const int lane = tid & 31;
    const int wr = warp >> 1;        // 0..1
    const int wc = warp & 1;         // 0..1
    const int g  = lane >> 2;        // 0..7
    const int tg = lane & 3;         // 0..3

    const int bx = blockIdx.x, by = blockIdx.y;
    const float* Ab = A + (size_t)by * GBM * K;
    const float* Bb = B + (size_t)bx * GBN;

    const int nc = K / GBK;

    // issue one K-chunk into stage (c % 3); 128 threads, 16 cp16 each
    auto issue = [&](int c) {
        u32* stg = smem_u + (c % 3) * STG_ELEMS;
        u32* As = stg;
        u32* Bs = stg + A_STG;
        const int k0 = c * GBK;
        #pragma unroll
        for (int p = 0; p < 8; p++) {          // A: 1024 x 16B chunks
            int id = tid + p * 128;
            int r = id >> 3, kc = (id & 7) * 4;
            cp16(&As[r * AS_STRIDE + kc], Ab + (size_t)r * K + k0 + kc);
        }
        #pragma unroll
        for (int p = 0; p < 8; p++) {          // B: 1024 x 16B chunks
            int id = tid + p * 128;
            int r = id >> 5, nc4 = (id & 31) * 4;
            cp16(&Bs[r * BS_STRIDE + nc4], Bb + (size_t)(k0 + r) * N + nc4);
        }
    };

    float acc[4][8][4];
    #pragma unroll
    for (int i = 0; i < 4; i++)
        #pragma unroll
        for (int j = 0; j < 8; j++)
            #pragma unroll
            for (int r = 0; r < 4; r++) acc[i][j][r] = 0.f;

    issue(0); CP_COMMIT();
    issue(1); CP_COMMIT();

    for (int c = 0; c < nc; c++) {
        CP_WAIT(1);            // chunk c resident
        __syncthreads();       // visible to all; compute(c-1) finished
        if (c + 2 < nc) issue(c + 2);
        CP_COMMIT();

        const u32* stg = smem_u + (c % 3) * STG_ELEMS;
        const u32* Ac = stg;
        const u32* Bc = stg + A_STG;

        #pragma unroll
        for (int ks = 0; ks < 4; ks++) {
            u32 af[4][4], bf[8][2];
            #pragma unroll
            for (int mt = 0; mt < 4; mt++) {
                int base = (wr*64 + mt*16 + g) * AS_STRIDE + ks*8 + tg;
                af[mt][0] = Ac[base];
                af[mt][1] = Ac[base + 8*AS_STRIDE];
                af[mt][2] = Ac[base + 4];
                af[mt][3] = Ac[base + 8*AS_STRIDE + 4];
            }
            #pragma unroll
            for (int nt = 0; nt < 8; nt++) {
                int col = wc*64 + nt*8 + g;
                int idx = (ks*8 + tg) * BS_STRIDE + col;
                bf[nt][0] = Bc[idx];
                bf[nt][1] = Bc[idx + 4*BS_STRIDE];
            }
            #pragma unroll
            for (int mt = 0; mt < 4; mt++)
                #pragma unroll
                for (int nt = 0; nt < 8; nt++)
                    mma_tf32(acc[mt][nt], af[mt], bf[nt]);
        }
    }

    float* Cb = C + (size_t)by * GBM * N + (size_t)bx * GBN;
    #pragma unroll
    for (int mt = 0; mt < 4; mt++) {
        int row = wr*64 + mt*16 + g;
        #pragma unroll
        for (int nt = 0; nt < 8; nt++) {
            int col = wc*64 + nt*8 + tg*2;
            *(float2*)(Cb + (size_t)row * N + col) =
                make_float2(acc[mt][nt][0], acc[mt][nt][1]);
            *(float2*)(Cb + (size_t)(row + 8) * N + col) =
                make_float2(acc[mt][nt][2], acc[mt][nt][3]);
        }
    }
}

// =====================================================================
// RoPE + V scale (sincos computed once per token).
// =====================================================================
__global__ __launch_bounds__(256) void rope_kernel(
    float* __restrict__ qkv, const int* __restrict__ positions)
{
    __shared__ float cs[64], sn[64];
    const int t = blockIdx.x;
    const int tid = threadIdx.x;
    float* row = qkv + (size_t)t * QKV_N;

    if (tid < 64) {
        float pos = (float)positions[t];
        float inv = powf(1.0e6f, -(float)tid * (1.0f / 64.0f));
        float fr = pos * inv;
        float s, c;
        sincosf(fr, &s, &c);
        cs[tid] = c; sn[tid] = s;
    }
    __syncthreads();

    for (int idx = tid; idx < 40 * 64; idx += 256) {
        int head = idx >> 6;
        int i = idx & 63;
        int base = (head < NH) ? head * HD : K_OFF + (head - NH) * HD;
        float c = cs[i], s = sn[i];
        float x1 = row[base + i];
        float x2 = row[base + i + 64];
        row[base + i]      = x1 * c - x2 * s;
        row[base + i + 64] = x2 * c + x1 * s;
    }
    for (int idx = tid; idx < NKH * VDIM; idx += 256) {
        row[V_OFF + idx] *= V_SCALE_C;
    }
}

// =====================================================================
// Prepack K: interleaved (hi,lo) bf16 pairs per K row.
// =====================================================================
__global__ __launch_bounds__(256) void prepack_k_kernel(
    const float* __restrict__ qkv)
{
    int idx = blockIdx.x * 256 + threadIdx.x;      // 524288
    int c  = idx & 31;
    int t  = (idx >> 5) & 2047;
    int kh = idx >> 16;
    float4 v = *(const float4*)(qkv + (size_t)t * QKV_N + K_OFF + kh * HD + c * 4);
    u32 h01, l01, h23, l23;
    split2(v.x, v.y, h01, l01);
    split2(v.z, v.w, h23, l23);
    g_kp[((kh << 11) + t) * 32 + c] = make_uint4(h01, l01, h23, l23);
}

// =====================================================================
// Prepack V: transposed key-pair-major, split hi/lo.
// =====================================================================
__global__ __launch_bounds__(256) void prepack_v_kernel(
    const float* __restrict__ qkv)
{
    int idx = blockIdx.x * 256 + threadIdx.x;      // 131072
    int c  = idx & 15;
    int kp = (idx >> 4) & 1023;
    int kh = idx >> 14;
    const float* r0 = qkv + (size_t)(2*kp)     * QKV_N + V_OFF + kh * VDIM + c * 4;
    const float* r1 = qkv + (size_t)(2*kp + 1) * QKV_N + V_OFF + kh * VDIM + c * 4;
    float4 a = *(const float4*)r0;
    float4 b = *(const float4*)r1;
    u32 h0, l0, h1, l1, h2, l2, h3, l3;
    split2(a.x, b.x, h0, l0);
    split2(a.y, b.y, h1, l1);
    split2(a.z, b.z, h2, l2);
    split2(a.w, b.w, h3, l3);
    size_t base = (((size_t)(kh << 10) + kp) * 2) * 16;
    g_vt[base + c]      = make_uint4(h0, h1, h2, h3);
    g_vt[base + 16 + c] = make_uint4(l0, l1, l2, l3);
}

// =====================================================================
// Flash attention (unchanged from passing round-10/11 config).
// =====================================================================
#define A_BM 64
#define KP2_STRIDE 136
#define VT_STRIDE  72
#define KSTG (64*KP2_STRIDE)
#define VSTG (2*32*VT_STRIDE)
#define STG  (KSTG + VSTG)
#define ATTN_SMEM (2 * STG * 4)

__global__ __launch_bounds__(128) void attn_kernel(
    const float* __restrict__ qkv, const float* __restrict__ sink,
    float* __restrict__ out)
{
    extern __shared__ u32 smem_a[];

    const int h  = blockIdx.y;
    const int m0 = blockIdx.x * A_BM;
    const int kh = h >> 2;

    const int tid  = threadIdx.x;
    const int warp = tid >> 5;
    const int lane = tid & 31;
    const int g  = lane >> 2;
    const int tg = lane & 3;
    const int wm = warp * 16;

    u32 qhi[8][4], qlo[8][4];
    {
        const float* Qr0 = qkv + (size_t)(m0 + wm + g) * QKV_N + h * HD;
        const float* Qr1 = Qr0 + 8 * (size_t)QKV_N;
        #pragma unroll
        for (int ks = 0; ks < 8; ks++) {
            int c0 = ks * 16 + 2 * tg;
            float2 x0 = *(const float2*)(Qr0 + c0);
            float2 x1 = *(const float2*)(Qr1 + c0);
            float2 x2 = *(const float2*)(Qr0 + c0 + 8);
            float2 x3 = *(const float2*)(Qr1 + c0 + 8);
            split2(x0.x, x0.y, qhi[ks][0], qlo[ks][0]);
            split2(x1.x, x1.y, qhi[ks][1], qlo[ks][1]);
            split2(x2.x, x2.y, qhi[ks][2], qlo[ks][2]);
            split2(x3.x, x3.y, qhi[ks][3], qlo[ks][3]);
        }
    }

    const float snk = sink[h];
    float m_r[2] = {snk, snk};
    float l_r[2] = {1.0f, 1.0f};
    float O[8][4];
    #pragma unroll
    for (int nt = 0; nt < 8; nt++)
        #pragma unroll
        for (int r = 0; r < 4; r++) O[nt][r] = 0.f;

    const int gi0 = m0 + wm + g;
    const int gi1 = gi0 + 8;

    int n0s = m0 - WINDOW_SZ;
    if (n0s < 0) n0s = 0;
    const int ntiles = (m0 - n0s) / 64 + 1;

    const uint4* Kp = g_kp + ((size_t)kh << 11) * 32;
    const uint4* Vp = g_vt + (((size_t)kh << 10) * 2) * 16;

    auto issue_tile = [&](int it) {
        int n0 = n0s + it * 64;
        u32* stg = smem_a + (it & 1) * STG;
        u32* KPb   = stg;
        u32* VThib = stg + KSTG;
        u32* VTlob = VThib + 32 * VT_STRIDE;
        #pragma unroll
        for (int p = 0; p < 16; p++) {
            int id = tid + p * 128;
            int r = id >> 5, c = id & 31;
            cp16(&KPb[r * KP2_STRIDE + 4*c], &Kp[(n0 + r) * 32 + c]);
        }
        int kp0 = n0 >> 1;
        #pragma unroll
        for (int p = 0; p < 8; p++) {
            int id = tid + p * 128;
            int kp = id >> 5, hl = (id >> 4) & 1, c = id & 15;
            u32* dst = (hl ? VTlob : VThib) + kp * VT_STRIDE + 4*c;
            cp16(dst, &Vp[((kp0 + kp) * 2 + hl) * 16 + c]);
        }
        CP_COMMIT();
    };

    issue_tile(0);

    for (int it = 0; it < ntiles; it++) {
        const int n0 = n0s + it * 64;
        if (it + 1 < ntiles) {
            issue_tile(it + 1);
            CP_WAIT(1);
        } else {
            CP_WAIT(0);
        }
        __syncthreads();

        u32* stg = smem_a + (it & 1) * STG;
        const u32* KP   = stg;
        const u32* VThi = stg + KSTG;
        const u32* VTlo = VThi + 32 * VT_STRIDE;

        float Sa[8][4];
        #pragma unroll
        for (int nt = 0; nt < 8; nt++)
            #pragma unroll
            for (int r = 0; r < 4; r++) Sa[nt][r] = 0.f;

        #pragma unroll
        for (int ks = 0; ks < 8; ks++) {
            #pragma unroll
            for (int nt = 0; nt < 8; nt++) {
                int base = (nt*8 + g) * KP2_STRIDE + 2*(ks*8 + tg);
                uint2 b0 = *(const uint2*)&KP[base];
                uint2 b1 = *(const uint2*)&KP[base + 8];
                u32 bh[2] = {b0.x, b1.x};
                u32 bl[2] = {b0.y, b1.y};
                mma_bf16(Sa[nt], qhi[ks], bh);
                mma_bf16(Sa[nt], qlo[ks], bh);
                mma_bf16(Sa[nt], qhi[ks], bl);
            }
        }

        #pragma unroll
        for (int nt = 0; nt < 8; nt++) {
            #pragma unroll
            for (int cc = 0; cc < 2; cc++) {
                int gj = n0 + nt*8 + 2*tg + cc;
                bool v0 = (gj <= gi0) && (gj + WINDOW_SZ > gi0);
                bool v1 = (gj <= gi1) && (gj + WINDOW_SZ > gi1);
                Sa[nt][cc]     = v0 ? Sa[nt][cc]     * SCALE_ATTN : -1.0e30f;
                Sa[nt][2 + cc] = v1 ? Sa[nt][2 + cc] * SCALE_ATTN : -1.0e30f;
            }
        }

        float tm0 = -1.0e30f, tm1 = -1.0e30f;
        #pragma unroll
        for (int nt = 0; nt < 8; nt++) {
            tm0 = fmaxf(tm0, fmaxf(Sa[nt][0], Sa[nt][1]));
            tm1 = fmaxf(tm1, fmaxf(Sa[nt][2], Sa[nt][3]));
        }
        tm0 = fmaxf(tm0, __shfl_xor_sync(0xffffffffu, tm0, 1));
        tm0 = fmaxf(tm0, __shfl_xor_sync(0xffffffffu, tm0, 2));
        tm1 = fmaxf(tm1, __shfl_xor_sync(0xffffffffu, tm1, 1));
        tm1 = fmaxf(tm1, __shfl_xor_sync(0xffffffffu, tm1, 2));

        float mn0 = fmaxf(m_r[0], tm0);
        float mn1 = fmaxf(m_r[1], tm1);
        float corr0 = __expf(m_r[0] - mn0);
        float corr1 = __expf(m_r[1] - mn1);
        m_r[0] = mn0; m_r[1] = mn1;

        float rs0 = 0.f, rs1 = 0.f;
        #pragma unroll
        for (int nt = 0; nt < 8; nt++) {
            #pragma unroll
            for (int cc = 0; cc < 2; cc++) {
                float p0 = __expf(Sa[nt][cc]     - mn0);
                float p1 = __expf(Sa[nt][2 + cc] - mn1);
                Sa[nt][cc]     = p0;
                Sa[nt][2 + cc] = p1;
                rs0 += p0; rs1 += p1;
            }
        }
        rs0 += __shfl_xor_sync(0xffffffffu, rs0, 1);
        rs0 += __shfl_xor_sync(0xffffffffu, rs0, 2);
        rs1 += __shfl_xor_sync(0xffffffffu, rs1, 1);
        rs1 += __shfl_xor_sync(0xffffffffu, rs1, 2);

        l_r[0] = l_r[0] * corr0 + rs0;
        l_r[1] = l_r[1] * corr1 + rs1;
        #pragma unroll
        for (int nt = 0; nt < 8; nt++) {
            O[nt][0] *= corr0; O[nt][1] *= corr0;
            O[nt][2] *= corr1; O[nt][3] *= corr1;
        }

        #pragma unroll
        for (int kq = 0; kq < 4; kq++) {
            u32 phi[4], plo[4];
            split2(Sa[2*kq][0],   Sa[2*kq][1],   phi[0], plo[0]);
            split2(Sa[2*kq][2],   Sa[2*kq][3],   phi[1], plo[1]);
            split2(Sa[2*kq+1][0], Sa[2*kq+1][1], phi[2], plo[2]);
            split2(Sa[2*kq+1][2], Sa[2*kq+1][3], phi[3], plo[3]);
            #pragma unroll
            for (int nt = 0; nt < 8; nt++) {
                int i0 = (kq*8 + tg) * VT_STRIDE + nt*8 + g;
                u32 vh[2], vl[2];
                vh[0] = VThi[i0];                 vl[0] = VTlo[i0];
                vh[1] = VThi[i0 + 4*VT_STRIDE];   vl[1] = VTlo[i0 + 4*VT_STRIDE];
                mma_bf16(O[nt], phi, vh);
                mma_bf16(O[nt], plo, vh);
                mma_bf16(O[nt], phi, vl);
            }
        }
        __syncthreads();
    }

    // epilogue — pre-round to tf32 for the Wo GEMM
    float inv0 = 1.0f / l_r[0];
    float inv1 = 1.0f / l_r[1];
    #pragma unroll
    for (int nt = 0; nt < 8; nt++) {
        int col = h * VDIM + nt*8 + 2*tg;
        float2 a = make_float2(__uint_as_float(f2tf32(O[nt][0] * inv0)),
                               __uint_as_float(f2tf32(O[nt][1] * inv0)));
        float2 b = make_float2(__uint_as_float(f2tf32(O[nt][2] * inv1)),
                               __uint_as_float(f2tf32(O[nt][3] * inv1)));
        *(float2*)(out + (size_t)gi0 * (NH * VDIM) + col) = a;
        *(float2*)(out + (size_t)gi1 * (NH * VDIM) + col) = b;
    }
}

// =====================================================================
// launch
// =====================================================================
extern "C" void kernel_launch(void* const* d_in, const int* in_sizes, int n_in,
                              void* d_out, int out_size)
{
    const int*   positions = (const int*)  d_in[0];
    const float* hidden    = (const float*)d_in[1];
    const float* Wqkv      = (const float*)d_in[2];
    const float* Wo        = (const float*)d_in[3];
    const float* sink      = (const float*)d_in[4];
    float* out = (float*)d_out;

    float *qkv, *attn, *hid_t, *wqkv_t, *wo_t;
    cudaGetSymbolAddress((void**)&qkv,    g_qkv);
    cudaGetSymbolAddress((void**)&attn,   g_attn);
    cudaGetSymbolAddress((void**)&hid_t,  g_hid_t);
    cudaGetSymbolAddress((void**)&wqkv_t, g_wqkv_t);
    cudaGetSymbolAddress((void**)&wo_t,   g_wo_t);

    cudaFuncSetAttribute(gemm_tf32_kernel,
                         cudaFuncAttributeMaxDynamicSharedMemorySize, GEMM_SMEM);
    cudaFuncSetAttribute(attn_kernel,
                         cudaFuncAttributeMaxDynamicSharedMemorySize, ATTN_SMEM);

    // 0) pre-round GEMM inputs to tf32
    tf32_round_kernel<<<(T_TOK*HID/4 + 255)/256, 256>>>(hidden, hid_t, T_TOK*HID/4);
    tf32_round_kernel<<<(HID*QKV_N/4 + 255)/256, 256>>>(Wqkv, wqkv_t, HID*QKV_N/4);
    tf32_round_kernel<<<(NH*VDIM*HID/4 + 255)/256, 256>>>(Wo, wo_t, NH*VDIM*HID/4);

    // 1) QKV projection
    {
        dim3 grid(QKV_N / GBN, T_TOK / GBM);
        gemm_tf32_kernel<<<grid, 128, GEMM_SMEM>>>(hid_t, wqkv_t, qkv,
                                                   T_TOK, QKV_N, HID);
    }
    // 2) RoPE + V scale
    rope_kernel<<<T_TOK, 256>>>(qkv, positions);
    // 3) prepack K and V
    prepack_k_kernel<<<2048, 256>>>(qkv);
    prepack_v_kernel<<<512, 256>>>(qkv);
    // 4) attention
    {
        dim3 grid(T_TOK / A_BM, NH);
        attn_kernel<<<grid, 128, ATTN_SMEM>>>(qkv, sink, attn);
    }
    // 5) output projection
    {
        dim3 grid(HID / GBN, T_TOK / GBM);
        gemm_tf32_kernel<<<grid, 128, GEMM_SMEM>>>(attn, wo_t, out,
                                                   T_TOK, HID, NH * VDIM);
    }
}

// round 14
// speedup vs baseline: 1.2121x; 1.2121x over previous
#include <cuda_runtime.h>
#include <cuda_bf16.h>
#include <cstdint>
#include <math.h>

typedef unsigned int u32;

// ---------------- problem constants ----------------
#define T_TOK   2048
#define HID     4096
#define NH      32
#define NKH     8
#define HD      128
#define VDIM    64
#define QKV_N   (NH*HD + NKH*HD + NKH*VDIM)   // 5632
#define K_OFF   (NH*HD)                        // 4096
#define V_OFF   (NH*HD + NKH*HD)               // 5120
#define WINDOW_SZ 1024
#define SCALE_ATTN 0.08838834764831845f        // 128^-0.5
#define V_SCALE_C  1.25f

// ---------------- scratch (no allocs allowed) ----------------
__device__ float g_qkv [T_TOK * QKV_N];
__device__ float g_attn[T_TOK * NH * VDIM];
__device__ uint4 g_kp[NKH * T_TOK * 32];            // prepacked K (8 MB)
__device__ uint4 g_vt[NKH * (T_TOK/2) * 2 * 16];    // prepacked V (4 MB)
__device__ u32 g_afh[T_TOK * HID];                  // hidden, frag-ordered
__device__ u32 g_bqf[QKV_N * HID];                  // Wqkv,   frag-ordered
__device__ u32 g_bof[HID * (NH*VDIM)];              // Wo,     frag-ordered
__device__ u32 g_afa[T_TOK * (NH*VDIM)];            // attn out, frag-ordered

// =====================================================================
// helpers
// =====================================================================
__device__ __forceinline__ u32 f2tf32(float f) {
    u32 r;
    asm("cvt.rna.tf32.f32 %0, %1;" : "=r"(r) : "f"(f));
    return r;
}

__device__ __forceinline__ void mma_tf32(float c[4], const u32 a[4],
                                         const u32 b[2]) {
    asm volatile(
        "mma.sync.aligned.m16n8k8.row.col.f32.tf32.tf32.f32 "
        "{%0,%1,%2,%3}, {%4,%5,%6,%7}, {%8,%9}, {%0,%1,%2,%3};\n"
        : "+f"(c[0]), "+f"(c[1]), "+f"(c[2]), "+f"(c[3])
        : "r"(a[0]), "r"(a[1]), "r"(a[2]), "r"(a[3]), "r"(b[0]), "r"(b[1]));
}

__device__ __forceinline__ void mma_bf16(float c[4], const u32 a[4],
                                         const u32 b[2]) {
    asm volatile(
        "mma.sync.aligned.m16n8k16.row.col.f32.bf16.bf16.f32 "
        "{%0,%1,%2,%3}, {%4,%5,%6,%7}, {%8,%9}, {%0,%1,%2,%3};\n"
        : "+f"(c[0]), "+f"(c[1]), "+f"(c[2]), "+f"(c[3])
        : "r"(a[0]), "r"(a[1]), "r"(a[2]), "r"(a[3]), "r"(b[0]), "r"(b[1]));
}

__device__ __forceinline__ void split2(float x, float y, u32& hi, u32& lo) {
    u32 bx = __float_as_uint(x), by = __float_as_uint(y);
    hi = __byte_perm(bx, by, 0x7632);
    float lx = x - __uint_as_float(bx & 0xffff0000u);
    float ly = y - __uint_as_float(by & 0xffff0000u);
    lo = __byte_perm(__float_as_uint(lx), __float_as_uint(ly), 0x7632);
}

__device__ __forceinline__ void cp16(void* smem_dst, const void* gmem_src) {
    u32 s = (u32)__cvta_generic_to_shared(smem_dst);
    asm volatile("cp.async.ca.shared.global [%0], [%1], 16;\n"
                 :: "r"(s), "l"(gmem_src));
}
#define CP_COMMIT() asm volatile("cp.async.commit_group;\n" ::: "memory")
#define CP_WAIT(N)  asm volatile("cp.async.wait_group %0;\n" :: "n"(N) : "memory")

// =====================================================================
// Prepack A into mma fragment order (tf32-rounded):
// A[M][K] f32 -> A'[M/16][K/8][lane 32][4]  (a0,a1,a2,a3 frag regs)
// grid (M/16, K/128), 256 threads.
// =====================================================================
__global__ __launch_bounds__(256) void prepack_afrag_kernel(
    const float* __restrict__ in, u32* __restrict__ out, int K)
{
    __shared__ float s[16][132];
    const int m16 = blockIdx.x;
    const int kc0 = blockIdx.y * 128;
    const int tid = threadIdx.x;

    #pragma unroll
    for (int i = 0; i < 8; i++) {
        int f = tid + i * 256;
        int r = f >> 7, col = f & 127;
        s[r][col] = in[(size_t)(m16 * 16 + r) * K + kc0 + col];
    }
    __syncthreads();

    const int K8 = K >> 3;
    #pragma unroll
    for (int i = 0; i < 2; i++) {
        int p = tid + i * 256;              // 0..511  = 16 ks x 32 lanes
        int ks = p >> 5, lane = p & 31;
        int g = lane >> 2, tg = lane & 3;
        uint4 v;
        v.x = f2tf32(s[g]    [ks*8 + tg]);
        v.y = f2tf32(s[g + 8][ks*8 + tg]);
        v.z = f2tf32(s[g]    [ks*8 + tg + 4]);
        v.w = f2tf32(s[g + 8][ks*8 + tg + 4]);
        ((uint4*)out)[((size_t)m16 * K8 + (kc0 >> 3) + ks) * 32 + lane] = v;
    }
}

// =====================================================================
// Prepack B into mma fragment order (tf32-rounded):
// W[K][N] f32 -> B'[N/8][K/8][lane 32][2]  (b0,b1 frag regs)
// grid (N/64, K/64), 256 threads.
// =====================================================================
__global__ __launch_bounds__(256) void prepack_bfrag_kernel(
    const float* __restrict__ W, u32* __restrict__ out, int K, int N)
{
    __shared__ float s[64][68];
    const int n0 = blockIdx.x * 64;
    const int k0 = blockIdx.y * 64;
    const int tid = threadIdx.x;

    #pragma unroll
    for (int i = 0; i < 16; i++) {
        int f = tid + i * 256;
        int r = f >> 6, c = f & 63;
        s[r][c] = W[(size_t)(k0 + r) * N + n0 + c];
    }
    __syncthreads();

    const int K8 = K >> 3;
    #pragma unroll
    for (int i = 0; i < 8; i++) {
        int p = tid + i * 256;              // 0..2047 = 8v x 8ks x 32 lanes
        int unit = p >> 5;                  // 0..63
        int v = unit >> 3, ks = unit & 7;
        int lane = p & 31;
        int g = lane >> 2, tg = lane & 3;
        uint2 w;
        w.x = f2tf32(s[ks*8 + tg]    [v*8 + g]);
        w.y = f2tf32(s[ks*8 + tg + 4][v*8 + g]);
        ((uint2*)out)[((size_t)(n0/8 + v) * K8 + (k0 >> 3) + ks) * 32 + lane] = w;
    }
}

// =====================================================================
// TF32 GEMM on frag-ordered operands, cp.async 3-stage pipeline.
// C[M,N] = A[M,K] * B[K,N]; 128x128 block, BK=32, 8 warps (2x4),
// warp tile 64x32. Frag loads are LDS.128 / LDS.64, conflict-free.
// =====================================================================
#define A_STG 4096                    // u32 per stage (128x32)
#define B_STG 4096                    // u32 per stage (32x128)
#define STG_ELEMS (A_STG + B_STG)     // 8192 u32 = 32 KB
#define GEMM_SMEM (3 * STG_ELEMS * 4) // 96 KB

__global__ __launch_bounds__(256, 2) void gemm_tf32_kernel(
    const u32* __restrict__ Af, const u32* __restrict__ Bf,
    float* __restrict__ C, int M, int N, int K)
{
    extern __shared__ u32 smem_u[];

    const int tid  = threadIdx.x;
    const int warp = tid >> 5;
    const int lane = tid & 31;
    const int wr = warp >> 2;         // 0..1
    const int wc = warp & 3;          // 0..3
    const int g  = lane >> 2;
    const int tg = lane & 3;

    const int bx = blockIdx.x, by = blockIdx.y;
    const int K8 = K >> 3;
    const int nc = K >> 5;            // BK=32 chunks

    // copy one chunk into stage (c % 3); all-contiguous 16B chunks
    auto issue = [&](int c) {
        u32* As = smem_u + (c % 3) * STG_ELEMS;
        u32* Bs = As + A_STG;
        #pragma unroll
        for (int p = 0; p < 4; p++) {          // A: 1024 x 16B
            int q = tid + p * 256;
            int unit = q >> 5, ln = q & 31;    // unit = i*4+ks
            const u32* src = Af +
                (((size_t)(by*8 + (unit >> 2)) * K8 + c*4 + (unit & 3)) * 32 + ln) * 4;
            cp16(&As[q * 4], src);
        }
        #pragma unroll
        for (int p = 0; p < 4; p++) {          // B: 1024 x 16B
            int q = tid + p * 256;
            int unit = q >> 4, half = q & 15;  // unit = v*4+ks
            const u32* src = Bf +
                ((size_t)(bx*16 + (unit >> 2)) * K8 + c*4 + (unit & 3)) * 64 + half * 4;
            cp16(&Bs[q * 4], src);
        }
    };

    float acc[4][4][4];
    #pragma unroll
    for (int i = 0; i < 4; i++)
        #pragma unroll
        for (int j = 0; j < 4; j++)
            #pragma unroll
            for (int r = 0; r < 4; r++) acc[i][j][r] = 0.f;

    issue(0); CP_COMMIT();
    issue(1); CP_COMMIT();

    for (int c = 0; c < nc; c++) {
        if (c + 1 < nc) { CP_WAIT(1); } else { CP_WAIT(0); }
        __syncthreads();
        if (c + 2 < nc) issue(c + 2);
        CP_COMMIT();

        const u32* As = smem_u + (c % 3) * STG_ELEMS;
        const u32* Bs = As + A_STG;

        #pragma unroll
        for (int ks = 0; ks < 4; ks++) {
            u32 af[4][4], bf[4][2];
            #pragma unroll
            for (int mt = 0; mt < 4; mt++) {
                uint4 v = *(const uint4*)&As[(((wr*4 + mt)*4 + ks)*32 + lane) * 4];
                af[mt][0] = v.x; af[mt][1] = v.y; af[mt][2] = v.z; af[mt][3] = v.w;
            }
            #pragma unroll
            for (int nt = 0; nt < 4; nt++) {
                uint2 w = *(const uint2*)&Bs[(((wc*4 + nt)*4 + ks)*32 + lane) * 2];
                bf[nt][0] = w.x; bf[nt][1] = w.y;
            }
            #pragma unroll
            for (int mt = 0; mt < 4; mt++)
                #pragma unroll
                for (int nt = 0; nt < 4; nt++)
                    mma_tf32(acc[mt][nt], af[mt], bf[nt]);
        }
    }

    float* Cb = C + (size_t)by * 128 * N + (size_t)bx * 128;
    #pragma unroll
    for (int mt = 0; mt < 4; mt++) {
        int row = wr*64 + mt*16 + g;
        #pragma unroll
        for (int nt = 0; nt < 4; nt++) {
            int col = wc*32 + nt*8 + tg*2;
            *(float2*)(Cb + (size_t)row * N + col) =
                make_float2(acc[mt][nt][0], acc[mt][nt][1]);
            *(float2*)(Cb + (size_t)(row + 8) * N + col) =
                make_float2(acc[mt][nt][2], acc[mt][nt][3]);
        }
    }
}

// =====================================================================
// RoPE + V scale (sincos computed once per token).
// =====================================================================
__global__ __launch_bounds__(256) void rope_kernel(
    float* __restrict__ qkv, const int* __restrict__ positions)
{
    __shared__ float cs[64], sn[64];
    const int t = blockIdx.x;
    const int tid = threadIdx.x;
    float* row = qkv + (size_t)t * QKV_N;

    if (tid < 64) {
        float pos = (float)positions[t];
        float inv = powf(1.0e6f, -(float)tid * (1.0f / 64.0f));
        float fr = pos * inv;
        float s, c;
        sincosf(fr, &s, &c);
        cs[tid] = c; sn[tid] = s;
    }
    __syncthreads();

    for (int idx = tid; idx < 40 * 64; idx += 256) {
        int head = idx >> 6;
        int i = idx & 63;
        int base = (head < NH) ? head * HD : K_OFF + (head - NH) * HD;
        float c = cs[i], s = sn[i];
        float x1 = row[base + i];
        float x2 = row[base + i + 64];
        row[base + i]      = x1 * c - x2 * s;
        row[base + i + 64] = x2 * c + x1 * s;
    }
    for (int idx = tid; idx < NKH * VDIM; idx += 256) {
        row[V_OFF + idx] *= V_SCALE_C;
    }
}

// =====================================================================
// Prepack K: interleaved (hi,lo) bf16 pairs per K row.
// =====================================================================
__global__ __launch_bounds__(256) void prepack_k_kernel(
    const float* __restrict__ qkv)
{
    int idx = blockIdx.x * 256 + threadIdx.x;      // 524288
    int c  = idx & 31;
    int t  = (idx >> 5) & 2047;
    int kh = idx >> 16;
    float4 v = *(const float4*)(qkv + (size_t)t * QKV_N + K_OFF + kh * HD + c * 4);
    u32 h01, l01, h23, l23;
    split2(v.x, v.y, h01, l01);
    split2(v.z, v.w, h23, l23);
    g_kp[((kh << 11) + t) * 32 + c] = make_uint4(h01, l01, h23, l23);
}

// =====================================================================
// Prepack V: transposed key-pair-major, split hi/lo.
// =====================================================================
__global__ __launch_bounds__(256) void prepack_v_kernel(
    const float* __restrict__ qkv)
{
    int idx = blockIdx.x * 256 + threadIdx.x;      // 131072
    int c  = idx & 15;
    int kp = (idx >> 4) & 1023;
    int kh = idx >> 14;
    const float* r0 = qkv + (size_t)(2*kp)     * QKV_N + V_OFF + kh * VDIM + c * 4;
    const float* r1 = qkv + (size_t)(2*kp + 1) * QKV_N + V_OFF + kh * VDIM + c * 4;
    float4 a = *(const float4*)r0;
    float4 b = *(const float4*)r1;
    u32 h0, l0, h1, l1, h2, l2, h3, l3;
    split2(a.x, b.x, h0, l0);
    split2(a.y, b.y, h1, l1);
    split2(a.z, b.z, h2, l2);
    split2(a.w, b.w, h3, l3);
    size_t base = (((size_t)(kh << 10) + kp) * 2) * 16;
    g_vt[base + c]      = make_uint4(h0, h1, h2, h3);
    g_vt[base + 16 + c] = make_uint4(l0, l1, l2, l3);
}

// =====================================================================
// Flash attention (passing round-10/11 config, unchanged).
// =====================================================================
#define A_BM 64
#define KP2_STRIDE 136
#define VT_STRIDE  72
#define KSTG (64*KP2_STRIDE)
#define VSTG (2*32*VT_STRIDE)
#define STG  (KSTG + VSTG)
#define ATTN_SMEM (2 * STG * 4)

__global__ __launch_bounds__(128) void attn_kernel(
    const float* __restrict__ qkv, const float* __restrict__ sink,
    float* __restrict__ out)
{
    extern __shared__ u32 smem_a[];

    const int h  = blockIdx.y;
    const int m0 = blockIdx.x * A_BM;
    const int kh = h >> 2;

    const int tid  = threadIdx.x;
    const int warp = tid >> 5;
    const int lane = tid & 31;
    const int g  = lane >> 2;
    const int tg = lane & 3;
    const int wm = warp * 16;

    u32 qhi[8][4], qlo[8][4];
    {
        const float* Qr0 = qkv + (size_t)(m0 + wm + g) * QKV_N + h * HD;
        const float* Qr1 = Qr0 + 8 * (size_t)QKV_N;
        #pragma unroll
        for (int ks = 0; ks < 8; ks++) {
            int c0 = ks * 16 + 2 * tg;
            float2 x0 = *(const float2*)(Qr0 + c0);
            float2 x1 = *(const float2*)(Qr1 + c0);
            float2 x2 = *(const float2*)(Qr0 + c0 + 8);
            float2 x3 = *(const float2*)(Qr1 + c0 + 8);
            split2(x0.x, x0.y, qhi[ks][0], qlo[ks][0]);
            split2(x1.x, x1.y, qhi[ks][1], qlo[ks][1]);
            split2(x2.x, x2.y, qhi[ks][2], qlo[ks][2]);
            split2(x3.x, x3.y, qhi[ks][3], qlo[ks][3]);
        }
    }

    const float snk = sink[h];
    float m_r[2] = {snk, snk};
    float l_r[2] = {1.0f, 1.0f};
    float O[8][4];
    #pragma unroll
    for (int nt = 0; nt < 8; nt++)
        #pragma unroll
        for (int r = 0; r < 4; r++) O[nt][r] = 0.f;

    const int gi0 = m0 + wm + g;
    const int gi1 = gi0 + 8;

    int n0s = m0 - WINDOW_SZ;
    if (n0s < 0) n0s = 0;
    const int ntiles = (m0 - n0s) / 64 + 1;

    const uint4* Kp = g_kp + ((size_t)kh << 11) * 32;
    const uint4* Vp = g_vt + (((size_t)kh << 10) * 2) * 16;

    auto issue_tile = [&](int it) {
        int n0 = n0s + it * 64;
        u32* stg = smem_a + (it & 1) * STG;
        u32* KPb   = stg;
        u32* VThib = stg + KSTG;
        u32* VTlob = VThib + 32 * VT_STRIDE;
        #pragma unroll
        for (int p = 0; p < 16; p++) {
            int id = tid + p * 128;
            int r = id >> 5, c = id & 31;
            cp16(&KPb[r * KP2_STRIDE + 4*c], &Kp[(n0 + r) * 32 + c]);
        }
        int kp0 = n0 >> 1;
        #pragma unroll
        for (int p = 0; p < 8; p++) {
            int id = tid + p * 128;
            int kp = id >> 5, hl = (id >> 4) & 1, c = id & 15;
            u32* dst = (hl ? VTlob : VThib) + kp * VT_STRIDE + 4*c;
            cp16(dst, &Vp[((kp0 + kp) * 2 + hl) * 16 + c]);
        }
        CP_COMMIT();
    };

    issue_tile(0);

    for (int it = 0; it < ntiles; it++) {
        const int n0 = n0s + it * 64;
        if (it + 1 < ntiles) {
            issue_tile(it + 1);
            CP_WAIT(1);
        } else {
            CP_WAIT(0);
        }
        __syncthreads();

        u32* stg = smem_a + (it & 1) * STG;
        const u32* KP   = stg;
        const u32* VThi = stg + KSTG;
        const u32* VTlo = VThi + 32 * VT_STRIDE;

        float Sa[8][4];
        #pragma unroll
        for (int nt = 0; nt < 8; nt++)
            #pragma unroll
            for (int r = 0; r < 4; r++) Sa[nt][r] = 0.f;

        #pragma unroll
        for (int ks = 0; ks < 8; ks++) {
            #pragma unroll
            for (int nt = 0; nt < 8; nt++) {
                int base = (nt*8 + g) * KP2_STRIDE + 2*(ks*8 + tg);
                uint2 b0 = *(const uint2*)&KP[base];
                uint2 b1 = *(const uint2*)&KP[base + 8];
                u32 bh[2] = {b0.x, b1.x};
                u32 bl[2] = {b0.y, b1.y};
                mma_bf16(Sa[nt], qhi[ks], bh);
                mma_bf16(Sa[nt], qlo[ks], bh);
                mma_bf16(Sa[nt], qhi[ks], bl);
            }
        }

        #pragma unroll
        for (int nt = 0; nt < 8; nt++) {
            #pragma unroll
            for (int cc = 0; cc < 2; cc++) {
                int gj = n0 + nt*8 + 2*tg + cc;
                bool v0 = (gj <= gi0) && (gj + WINDOW_SZ > gi0);
                bool v1 = (gj <= gi1) && (gj + WINDOW_SZ > gi1);
                Sa[nt][cc]     = v0 ? Sa[nt][cc]     * SCALE_ATTN : -1.0e30f;
                Sa[nt][2 + cc] = v1 ? Sa[nt][2 + cc] * SCALE_ATTN : -1.0e30f;
            }
        }

        float tm0 = -1.0e30f, tm1 = -1.0e30f;
        #pragma unroll
        for (int nt = 0; nt < 8; nt++) {
            tm0 = fmaxf(tm0, fmaxf(Sa[nt][0], Sa[nt][1]));
            tm1 = fmaxf(tm1, fmaxf(Sa[nt][2], Sa[nt][3]));
        }
        tm0 = fmaxf(tm0, __shfl_xor_sync(0xffffffffu, tm0, 1));
        tm0 = fmaxf(tm0, __shfl_xor_sync(0xffffffffu, tm0, 2));
        tm1 = fmaxf(tm1, __shfl_xor_sync(0xffffffffu, tm1, 1));
        tm1 = fmaxf(tm1, __shfl_xor_sync(0xffffffffu, tm1, 2));

        float mn0 = fmaxf(m_r[0], tm0);
        float mn1 = fmaxf(m_r[1], tm1);
        float corr0 = __expf(m_r[0] - mn0);
        float corr1 = __expf(m_r[1] - mn1);
        m_r[0] = mn0; m_r[1] = mn1;

        float rs0 = 0.f, rs1 = 0.f;
        #pragma unroll
        for (int nt = 0; nt < 8; nt++) {
            #pragma unroll
            for (int cc = 0; cc < 2; cc++) {
                float p0 = __expf(Sa[nt][cc]     - mn0);
                float p1 = __expf(Sa[nt][2 + cc] - mn1);
                Sa[nt][cc]     = p0;
                Sa[nt][2 + cc] = p1;
                rs0 += p0; rs1 += p1;
            }
        }
        rs0 += __shfl_xor_sync(0xffffffffu, rs0, 1);
        rs0 += __shfl_xor_sync(0xffffffffu, rs0, 2);
        rs1 += __shfl_xor_sync(0xffffffffu, rs1, 1);
        rs1 += __shfl_xor_sync(0xffffffffu, rs1, 2);

        l_r[0] = l_r[0] * corr0 + rs0;
        l_r[1] = l_r[1] * corr1 + rs1;
        #pragma unroll
        for (int nt = 0; nt < 8; nt++) {
            O[nt][0] *= corr0; O[nt][1] *= corr0;
            O[nt][2] *= corr1; O[nt][3] *= corr1;
        }

        #pragma unroll
        for (int kq = 0; kq < 4; kq++) {
            u32 phi[4], plo[4];
            split2(Sa[2*kq][0],   Sa[2*kq][1],   phi[0], plo[0]);
            split2(Sa[2*kq][2],   Sa[2*kq][3],   phi[1], plo[1]);
            split2(Sa[2*kq+1][0], Sa[2*kq+1][1], phi[2], plo[2]);
            split2(Sa[2*kq+1][2], Sa[2*kq+1][3], phi[3], plo[3]);
            #pragma unroll
            for (int nt = 0; nt < 8; nt++) {
                int i0 = (kq*8 + tg) * VT_STRIDE + nt*8 + g;
                u32 vh[2], vl[2];
                vh[0] = VThi[i0];                 vl[0] = VTlo[i0];
                vh[1] = VThi[i0 + 4*VT_STRIDE];   vl[1] = VTlo[i0 + 4*VT_STRIDE];
                mma_bf16(O[nt], phi, vh);
                mma_bf16(O[nt], plo, vh);
                mma_bf16(O[nt], phi, vl);
            }
        }
        __syncthreads();
    }

    // epilogue — tf32-rounded fp32 (Wo GEMM prepack re-rounds, idempotent)
    float inv0 = 1.0f / l_r[0];
    float inv1 = 1.0f / l_r[1];
    #pragma unroll
    for (int nt = 0; nt < 8; nt++) {
        int col = h * VDIM + nt*8 + 2*tg;
        float2 a = make_float2(__uint_as_float(f2tf32(O[nt][0] * inv0)),
                               __uint_as_float(f2tf32(O[nt][1] * inv0)));
        float2 b = make_float2(__uint_as_float(f2tf32(O[nt][2] * inv1)),
                               __uint_as_float(f2tf32(O[nt][3] * inv1)));
        *(float2*)(out + (size_t)gi0 * (NH * VDIM) + col) = a;
        *(float2*)(out + (size_t)gi1 * (NH * VDIM) + col) = b;
    }
}

// =====================================================================
// launch
// =====================================================================
extern "C" void kernel_launch(void* const* d_in, const int* in_sizes, int n_in,
                              void* d_out, int out_size)
{
    const int*   positions = (const int*)  d_in[0];
    const float* hidden    = (const float*)d_in[1];
    const float* Wqkv      = (const float*)d_in[2];
    const float* Wo        = (const float*)d_in[3];
    const float* sink      = (const float*)d_in[4];
    float* out = (float*)d_out;

    float *qkv, *attn;
    u32 *afh, *bqf, *bof, *afa;
    cudaGetSymbolAddress((void**)&qkv,  g_qkv);
    cudaGetSymbolAddress((void**)&attn, g_attn);
    cudaGetSymbolAddress((void**)&afh,  g_afh);
    cudaGetSymbolAddress((void**)&bqf,  g_bqf);
    cudaGetSymbolAddress((void**)&bof,  g_bof);
    cudaGetSymbolAddress((void**)&afa,  g_afa);

    cudaFuncSetAttribute(gemm_tf32_kernel,
                         cudaFuncAttributeMaxDynamicSharedMemorySize, GEMM_SMEM);
    cudaFuncSetAttribute(attn_kernel,
                         cudaFuncAttributeMaxDynamicSharedMemorySize, ATTN_SMEM);

    // 0) prepack GEMM operands into fragment order (tf32-rounded)
    prepack_afrag_kernel<<<dim3(T_TOK/16, HID/128), 256>>>(hidden, afh, HID);
    prepack_bfrag_kernel<<<dim3(QKV_N/64, HID/64), 256>>>(Wqkv, bqf, HID, QKV_N);
    prepack_bfrag_kernel<<<dim3(HID/64, (NH*VDIM)/64), 256>>>(Wo, bof, NH*VDIM, HID);

    // 1) QKV projection
    gemm_tf32_kernel<<<dim3(QKV_N/128, T_TOK/128), 256, GEMM_SMEM>>>(
        afh, bqf, qkv, T_TOK, QKV_N, HID);

    // 2) RoPE + V scale
    rope_kernel<<<T_TOK, 256>>>(qkv, positions);

    // 3) prepack K and V for attention
    prepack_k_kernel<<<2048, 256>>>(qkv);
    prepack_v_kernel<<<512, 256>>>(qkv);

    // 4) attention
    attn_kernel<<<dim3(T_TOK/A_BM, NH), 128, ATTN_SMEM>>>(qkv, sink, attn);

    // 5) reorder attention output into fragment order, then Wo projection
    prepack_afrag_kernel<<<dim3(T_TOK/16, (NH*VDIM)/128), 256>>>(attn, afa, NH*VDIM);
    gemm_tf32_kernel<<<dim3(HID/128, T_TOK/128), 256, GEMM_SMEM>>>(
        afa, bof, out, T_TOK, HID, NH*VDIM);
}